// round 1
// baseline (speedup 1.0000x reference)
#include <cuda_runtime.h>
#include <math.h>

#define B_    2
#define N_    2048
#define DIM_  2048
#define H_    16
#define D_    128
#define M_    (B_*N_)          // 4096 rows (b*n flattened)
#define E3_   (3*H_*D_)        // 6144
#define INNER (H_*D_)          // 2048
#define SCALE_ 0.08838834764831845f   // 128^-0.5

// ---------------- scratch (allocation-free: __device__ globals) ----------------
__device__ float g_qkv[(size_t)M_ * E3_];          // [b*n][6144]
__device__ float g_q[(size_t)B_*H_*N_*D_];         // [b][h][n][d]
__device__ float g_k[(size_t)B_*H_*N_*D_];
__device__ float g_v[(size_t)B_*H_*N_*D_];
__device__ float g_attn[(size_t)M_ * INNER];       // [b][n][h*128+d]
__device__ float g_proj[(size_t)M_ * DIM_];        // pre-layernorm

// ---------------- SGEMM (NT): C[M,N] = A[M,K] * B[N,K]^T, all row-major ----------------
__global__ __launch_bounds__(256) void sgemm_nt(const float* __restrict__ A,
                                                const float* __restrict__ Bm,
                                                float* __restrict__ C,
                                                int M, int N, int K)
{
    __shared__ float As[16][132];   // [k][m], padded
    __shared__ float Bs[16][132];   // [k][n], padded
    const int bm = blockIdx.y * 128;
    const int bn = blockIdx.x * 128;
    const int tid = threadIdx.x;
    const int tx = tid & 15, ty = tid >> 4;

    float acc[8][8];
#pragma unroll
    for (int i = 0; i < 8; i++)
#pragma unroll
        for (int j = 0; j < 8; j++) acc[i][j] = 0.f;

    const float* Ab = A + (size_t)bm * K;
    const float* Bb = Bm + (size_t)bn * K;

    for (int k0 = 0; k0 < K; k0 += 16) {
#pragma unroll
        for (int i = 0; i < 2; i++) {
            int lin = tid + i * 256;
            int row = lin >> 2;
            int c4  = (lin & 3) << 2;
            float4 av = *(const float4*)&Ab[(size_t)row * K + k0 + c4];
            As[c4+0][row] = av.x; As[c4+1][row] = av.y;
            As[c4+2][row] = av.z; As[c4+3][row] = av.w;
            float4 bv = *(const float4*)&Bb[(size_t)row * K + k0 + c4];
            Bs[c4+0][row] = bv.x; Bs[c4+1][row] = bv.y;
            Bs[c4+2][row] = bv.z; Bs[c4+3][row] = bv.w;
        }
        __syncthreads();
#pragma unroll
        for (int kk = 0; kk < 16; kk++) {
            float a[8], b[8];
            *(float4*)&a[0] = *(float4*)&As[kk][ty*8];
            *(float4*)&a[4] = *(float4*)&As[kk][ty*8 + 4];
            *(float4*)&b[0] = *(float4*)&Bs[kk][tx*8];
            *(float4*)&b[4] = *(float4*)&Bs[kk][tx*8 + 4];
#pragma unroll
            for (int i = 0; i < 8; i++)
#pragma unroll
                for (int j = 0; j < 8; j++)
                    acc[i][j] += a[i] * b[j];
        }
        __syncthreads();
    }

#pragma unroll
    for (int i = 0; i < 8; i++) {
        float* Crow = C + (size_t)(bm + ty*8 + i) * N + bn + tx*8;
        *(float4*)&Crow[0] = make_float4(acc[i][0], acc[i][1], acc[i][2], acc[i][3]);
        *(float4*)&Crow[4] = make_float4(acc[i][4], acc[i][5], acc[i][6], acc[i][7]);
    }
}

// ---------------- RoPE + scale + head transpose ----------------
// qkv[b,n,e] -> q/k/v[b,h,n,d] with rotary applied (full 128-dim rotation)
__global__ __launch_bounds__(128) void rotary_kernel(const float* __restrict__ qkv,
                                                     const float* __restrict__ rope)
{
    const int n  = blockIdx.x;
    const int bh = blockIdx.y;           // b*16 + h
    const int h  = bh & 15;
    const int d  = threadIdx.x;          // 0..127

    const float f = rope[n * D_ + d];
    float sv, cv;
    sincosf(f, &sv, &cv);

    const int   p   = (d < 64) ? d + 64 : d - 64;
    const float sgn = (d < 64) ? -1.f : 1.f;

    // base row of qkv for this (b,n)
    const size_t base = ((size_t)(bh >> 4) * N_ + n) * E3_ + h * D_;
    const float qd = qkv[base + d],        qp = qkv[base + p];
    const float kd = qkv[base + 2048 + d], kp = qkv[base + 2048 + p];
    const float vd = qkv[base + 4096 + d], vp = qkv[base + 4096 + p];

    const size_t o = ((size_t)bh * N_ + n) * D_ + d;
    g_q[o] = (qd * cv + sgn * qp * sv) * SCALE_;
    g_k[o] =  kd * cv + sgn * kp * sv;
    g_v[o] =  vd * cv + sgn * vp * sv;
}

// ---------------- causal flash attention ----------------
// BR=64 query rows x BC=64 key cols per tile. 256 threads: thread = (r, cg),
// r = query row (0..63), cg in 0..3 owns cols {4*jj+cg} and d-chunks {q*16+cg*4}.
#define FLASH_SMEM ((3*64*132 + 64*68) * 4)

__global__ __launch_bounds__(256) void flash_kernel()
{
    extern __shared__ float sm[];
    float* Qs = sm;                  // [64][132]
    float* Ks = sm + 64*132;         // [64][132]
    float* Vs = sm + 2*64*132;       // [64][132]
    float* Ps = sm + 3*64*132;       // [64][68]

    const int ti = blockIdx.x;       // query tile (32)
    const int bh = blockIdx.y;       // b*16+h (32)
    const int b  = bh >> 4, h = bh & 15;

    const float* Qg = g_q + (size_t)bh * (N_ * D_);
    const float* Kg = g_k + (size_t)bh * (N_ * D_);
    const float* Vg = g_v + (size_t)bh * (N_ * D_);

    const int tid = threadIdx.x;
    const int r = tid >> 2, cg = tid & 3;

    // load Q tile
    for (int i = tid; i < 64*32; i += 256) {
        int row = i >> 5, c = (i & 31) << 2;
        *(float4*)&Qs[row*132 + c] = *(const float4*)&Qg[(size_t)(ti*64 + row)*D_ + c];
    }

    float m = -3.0e38f, l = 0.f;
    float4 O[8];
#pragma unroll
    for (int q = 0; q < 8; q++) O[q] = make_float4(0.f, 0.f, 0.f, 0.f);

    for (int j = 0; j <= ti; ++j) {
        __syncthreads();   // prev-iter Vs/Ps consumed; Qs ready (iter 0)
        for (int i = tid; i < 64*32; i += 256) {
            int row = i >> 5, c = (i & 31) << 2;
            *(float4*)&Ks[row*132 + c] = *(const float4*)&Kg[(size_t)(j*64 + row)*D_ + c];
            *(float4*)&Vs[row*132 + c] = *(const float4*)&Vg[(size_t)(j*64 + row)*D_ + c];
        }
        __syncthreads();

        // S = Q K^T for this thread's 16 columns
        float s[16];
#pragma unroll
        for (int jj = 0; jj < 16; jj++) s[jj] = 0.f;
#pragma unroll 4
        for (int d4 = 0; d4 < 128; d4 += 4) {
            float4 q4 = *(float4*)&Qs[r*132 + d4];
#pragma unroll
            for (int jj = 0; jj < 16; jj++) {
                float4 k4 = *(float4*)&Ks[(jj*4 + cg)*132 + d4];
                s[jj] += q4.x*k4.x + q4.y*k4.y + q4.z*k4.z + q4.w*k4.w;
            }
        }
        if (j == ti) {      // causal mask on the diagonal tile
#pragma unroll
            for (int jj = 0; jj < 16; jj++)
                if (jj*4 + cg > r) s[jj] = -3.0e38f;
        }

        // online softmax (4 lanes per row cooperate)
        float mt = s[0];
#pragma unroll
        for (int jj = 1; jj < 16; jj++) mt = fmaxf(mt, s[jj]);
        mt = fmaxf(mt, __shfl_xor_sync(0xffffffffu, mt, 1));
        mt = fmaxf(mt, __shfl_xor_sync(0xffffffffu, mt, 2));
        float mnew = fmaxf(m, mt);

        float lt = 0.f;
#pragma unroll
        for (int jj = 0; jj < 16; jj++) {
            float p = __expf(s[jj] - mnew);
            Ps[r*68 + jj*4 + cg] = p;
            lt += p;
        }
        lt += __shfl_xor_sync(0xffffffffu, lt, 1);
        lt += __shfl_xor_sync(0xffffffffu, lt, 2);

        float alpha = __expf(m - mnew);
        l = l * alpha + lt;
        m = mnew;
#pragma unroll
        for (int q = 0; q < 8; q++) {
            O[q].x *= alpha; O[q].y *= alpha; O[q].z *= alpha; O[q].w *= alpha;
        }
        __syncthreads();   // Ps visible

        // O += P V  (thread owns d = q*16 + cg*4 + 0..3)
        for (int jj2 = 0; jj2 < 64; ++jj2) {
            float p = Ps[r*68 + jj2];
            const float* vrow = &Vs[jj2*132 + cg*4];
#pragma unroll
            for (int q = 0; q < 8; q++) {
                float4 v4 = *(const float4*)&vrow[q*16];
                O[q].x += p*v4.x; O[q].y += p*v4.y; O[q].z += p*v4.z; O[q].w += p*v4.w;
            }
        }
    }

    // normalize and write to [b][n][h*128+d]
    const float inv = 1.f / l;
    const int n = ti*64 + r;
    const size_t ob = ((size_t)(b*N_ + n)) * INNER + h*D_ + cg*4;
#pragma unroll
    for (int q = 0; q < 8; q++) {
        float4 o = O[q];
        o.x *= inv; o.y *= inv; o.z *= inv; o.w *= inv;
        *(float4*)&g_attn[ob + q*16] = o;
    }
}

// ---------------- layernorm ----------------
__global__ __launch_bounds__(256) void ln_kernel(const float* __restrict__ in,
                                                 const float* __restrict__ g,
                                                 float* __restrict__ out)
{
    const int row = blockIdx.x;
    const int tid = threadIdx.x;
    const float* x = in + (size_t)row * DIM_;

    float v[8];
    float s = 0.f, ss = 0.f;
#pragma unroll
    for (int i = 0; i < 8; i++) {
        v[i] = x[tid + i*256];
        s += v[i]; ss += v[i]*v[i];
    }
#pragma unroll
    for (int o = 16; o > 0; o >>= 1) {
        s  += __shfl_xor_sync(0xffffffffu, s,  o);
        ss += __shfl_xor_sync(0xffffffffu, ss, o);
    }
    __shared__ float sbuf[16];
    if ((tid & 31) == 0) { sbuf[tid>>5] = s; sbuf[8 + (tid>>5)] = ss; }
    __syncthreads();
    s = 0.f; ss = 0.f;
#pragma unroll
    for (int i = 0; i < 8; i++) { s += sbuf[i]; ss += sbuf[8+i]; }

    const float mean = s * (1.f/DIM_);
    const float var  = ss * (1.f/DIM_) - mean*mean;
    const float inv  = rsqrtf(var + 1e-5f);
#pragma unroll
    for (int i = 0; i < 8; i++) {
        int c = tid + i*256;
        out[(size_t)row*DIM_ + c] = (v[i] - mean) * inv * g[c];
    }
}

// ---------------- launch ----------------
extern "C" void kernel_launch(void* const* d_in, const int* in_sizes, int n_in,
                              void* d_out, int out_size)
{
    (void)in_sizes; (void)n_in; (void)out_size;
    const float* x     = (const float*)d_in[0];
    // d_in[1] = mask: all True in this problem -> no-op beyond causal mask
    const float* rope  = (const float*)d_in[2];
    const float* w_qkv = (const float*)d_in[3];
    const float* w_out = (const float*)d_in[4];
    const float* g     = (const float*)d_in[5];
    float* out = (float*)d_out;

    float *qkv, *attn, *proj;
    cudaGetSymbolAddress((void**)&qkv,  g_qkv);
    cudaGetSymbolAddress((void**)&attn, g_attn);
    cudaGetSymbolAddress((void**)&proj, g_proj);

    cudaFuncSetAttribute(flash_kernel,
                         cudaFuncAttributeMaxDynamicSharedMemorySize, FLASH_SMEM);

    // 1) qkv = x @ w_qkv^T        [4096,2048] x [6144,2048]^T
    sgemm_nt<<<dim3(E3_/128, M_/128), 256>>>(x, w_qkv, qkv, M_, E3_, 2048);
    // 2) RoPE + scale + transpose to [b,h,n,d]
    rotary_kernel<<<dim3(N_, B_*H_), 128>>>(qkv, rope);
    // 3) causal flash attention -> [b,n,inner]
    flash_kernel<<<dim3(N_/64, B_*H_), 256, FLASH_SMEM>>>();
    // 4) proj = attn @ w_out^T    [4096,2048] x [2048,2048]^T
    sgemm_nt<<<dim3(DIM_/128, M_/128), 256>>>(attn, w_out, proj, M_, DIM_, 2048);
    // 5) layernorm
    ln_kernel<<<M_, 256>>>(proj, g, out);
}

// round 3
// speedup vs baseline: 3.3395x; 3.3395x over previous
#include <cuda_runtime.h>
#include <math.h>
#include <stdint.h>

#define B_    2
#define N_    2048
#define DIM_  2048
#define H_    16
#define D_    128
#define M_    (B_*N_)          // 4096
#define E3_   (3*H_*D_)        // 6144
#define INNER (H_*D_)          // 2048
#define SCALE_ 0.08838834764831845f

// ---------------- scratch ----------------
__device__ float g_qkv[(size_t)M_ * E3_];
__device__ float g_q[(size_t)B_*H_*N_*D_];   // tf32-rounded
__device__ float g_k[(size_t)B_*H_*N_*D_];   // tf32-rounded
__device__ float g_v[(size_t)B_*H_*N_*D_];   // tf32-rounded
__device__ float g_attn[(size_t)M_ * INNER];
__device__ float g_proj[(size_t)M_ * DIM_];

// ---------------- tf32 helpers ----------------
__device__ __forceinline__ uint32_t f2tf(float x) {
    uint32_t u;
    asm("cvt.rna.tf32.f32 %0, %1;" : "=r"(u) : "f"(x));
    return u;
}
__device__ __forceinline__ void mma8(float* c,
                                     uint32_t a0, uint32_t a1, uint32_t a2, uint32_t a3,
                                     uint32_t b0, uint32_t b1) {
    asm volatile("mma.sync.aligned.m16n8k8.row.col.f32.tf32.tf32.f32 "
                 "{%0,%1,%2,%3}, {%4,%5,%6,%7}, {%8,%9}, {%0,%1,%2,%3};"
                 : "+f"(c[0]), "+f"(c[1]), "+f"(c[2]), "+f"(c[3])
                 : "r"(a0), "r"(a1), "r"(a2), "r"(a3), "r"(b0), "r"(b1));
}

// ---------------- tf32 GEMM (NT): C[M,N] = A[M,K] * B[N,K]^T ----------------
// 256 threads, BM=128, BN=128, BK=16. Warp grid 2(m) x 4(n); warp tile 64x32.
__global__ __launch_bounds__(256) void gemm_tf32(const float* __restrict__ A,
                                                 const float* __restrict__ Bm,
                                                 float* __restrict__ C,
                                                 int M, int N, int K)
{
    __shared__ uint32_t As[128][20];   // [m][k], pad 4
    __shared__ uint32_t Bs[128][20];   // [n][k], pad 4
    const int bm = blockIdx.y * 128;
    const int bn = blockIdx.x * 128;
    const int tid = threadIdx.x;
    const int warp = tid >> 5, lane = tid & 31;
    const int lr = lane >> 2, lc = lane & 3;
    const int wm = (warp & 1) * 64;
    const int wn = (warp >> 1) * 32;

    float acc[4][4][4];
#pragma unroll
    for (int i = 0; i < 4; i++)
#pragma unroll
        for (int j = 0; j < 4; j++)
#pragma unroll
            for (int q = 0; q < 4; q++) acc[i][j][q] = 0.f;

    const float* Ab = A + (size_t)bm * K;
    const float* Bb = Bm + (size_t)bn * K;

    for (int k0 = 0; k0 < K; k0 += 16) {
#pragma unroll
        for (int i = 0; i < 2; i++) {
            int lin = tid + i * 256;
            int row = lin >> 2;
            int cc  = (lin & 3) << 2;
            float4 av = *(const float4*)&Ab[(size_t)row * K + k0 + cc];
            uint4 au = make_uint4(f2tf(av.x), f2tf(av.y), f2tf(av.z), f2tf(av.w));
            *(uint4*)&As[row][cc] = au;
            float4 bv = *(const float4*)&Bb[(size_t)row * K + k0 + cc];
            uint4 bu = make_uint4(f2tf(bv.x), f2tf(bv.y), f2tf(bv.z), f2tf(bv.w));
            *(uint4*)&Bs[row][cc] = bu;
        }
        __syncthreads();
#pragma unroll
        for (int k8 = 0; k8 < 16; k8 += 8) {
            uint32_t af[4][4];
#pragma unroll
            for (int mt = 0; mt < 4; mt++) {
                int m = wm + mt * 16;
                af[mt][0] = As[m + lr][k8 + lc];
                af[mt][1] = As[m + 8 + lr][k8 + lc];
                af[mt][2] = As[m + lr][k8 + 4 + lc];
                af[mt][3] = As[m + 8 + lr][k8 + 4 + lc];
            }
#pragma unroll
            for (int nt = 0; nt < 4; nt++) {
                int n = wn + nt * 8;
                uint32_t b0 = Bs[n + lr][k8 + lc];
                uint32_t b1 = Bs[n + lr][k8 + 4 + lc];
#pragma unroll
                for (int mt = 0; mt < 4; mt++)
                    mma8(acc[mt][nt], af[mt][0], af[mt][1], af[mt][2], af[mt][3], b0, b1);
            }
        }
        __syncthreads();
    }

#pragma unroll
    for (int mt = 0; mt < 4; mt++) {
        int r1 = bm + wm + mt * 16 + lr;
#pragma unroll
        for (int nt = 0; nt < 4; nt++) {
            int col = bn + wn + nt * 8 + 2 * lc;
            *(float2*)&C[(size_t)r1 * N + col]       = make_float2(acc[mt][nt][0], acc[mt][nt][1]);
            *(float2*)&C[(size_t)(r1 + 8) * N + col] = make_float2(acc[mt][nt][2], acc[mt][nt][3]);
        }
    }
}

// ---------------- RoPE + scale + transpose (+ tf32 round) ----------------
__global__ __launch_bounds__(128) void rotary_kernel(const float* __restrict__ qkv,
                                                     const float* __restrict__ rope)
{
    const int n  = blockIdx.x;
    const int bh = blockIdx.y;
    const int h  = bh & 15;
    const int d  = threadIdx.x;

    const float f = rope[n * D_ + d];
    float sv, cv;
    sincosf(f, &sv, &cv);
    const int   p   = (d < 64) ? d + 64 : d - 64;
    const float sgn = (d < 64) ? -1.f : 1.f;

    const size_t base = ((size_t)(bh >> 4) * N_ + n) * E3_ + h * D_;
    const float qd = qkv[base + d],        qp = qkv[base + p];
    const float kd = qkv[base + 2048 + d], kp = qkv[base + 2048 + p];
    const float vd = qkv[base + 4096 + d], vp = qkv[base + 4096 + p];

    const size_t o = ((size_t)bh * N_ + n) * D_ + d;
    g_q[o] = __uint_as_float(f2tf((qd * cv + sgn * qp * sv) * SCALE_));
    g_k[o] = __uint_as_float(f2tf(kd * cv + sgn * kp * sv));
    g_v[o] = __uint_as_float(f2tf(vd * cv + sgn * vp * sv));
}

// ---------------- flash attention, tf32 mma ----------------
// BR=128 query rows, BC=64 keys per step, D=128. 256 threads = 8 warps.
// Warp w owns m-tile rows [16w, 16w+16): computes full 64-col S rows and full
// 128-d output rows. Q [128][132], K [64][132], V [64][136], P [128][68].
#define FQ_STRIDE 132
#define FV_STRIDE 136
#define FP_STRIDE 68
#define FSMEM ((128*FQ_STRIDE + 64*FQ_STRIDE + 64*FV_STRIDE + 128*FP_STRIDE) * 4)

__global__ __launch_bounds__(256) void flash_tf32()
{
    extern __shared__ uint32_t sm[];
    uint32_t* Qs = sm;                         // [128][132]
    uint32_t* Ks = Qs + 128 * FQ_STRIDE;       // [64][132]
    uint32_t* Vs = Ks + 64 * FQ_STRIDE;        // [64][136]
    uint32_t* Ps = Vs + 64 * FV_STRIDE;        // [128][68]

    const int ti = (gridDim.x - 1) - blockIdx.x;  // big tiles first
    const int bh = blockIdx.y;
    const int b  = bh >> 4, h = bh & 15;

    const float* Qg = g_q + (size_t)bh * (N_ * D_);
    const float* Kg = g_k + (size_t)bh * (N_ * D_);
    const float* Vg = g_v + (size_t)bh * (N_ * D_);

    const int tid = threadIdx.x;
    const int warp = tid >> 5, lane = tid & 31;
    const int lr = lane >> 2, lc = lane & 3;
    const int m0 = warp * 16;

    // load Q tile (tf32 bits already)
    for (int i = tid; i < 128 * 32; i += 256) {
        int row = i >> 5, c = (i & 31) << 2;
        *(uint4*)&Qs[row * FQ_STRIDE + c] =
            *(const uint4*)&Qg[(size_t)(ti * 128 + row) * D_ + c];
    }

    float m1 = -3.0e38f, m2 = -3.0e38f, l1 = 0.f, l2 = 0.f;
    float O[16][4];
#pragma unroll
    for (int nt = 0; nt < 16; nt++)
#pragma unroll
        for (int q = 0; q < 4; q++) O[nt][q] = 0.f;

    const int jmax = 2 * ti + 1;
    for (int j = 0; j <= jmax; ++j) {
        __syncthreads();   // prev PV done (Vs reusable); Qs ready on iter 0
        for (int i = tid; i < 64 * 32; i += 256) {
            int row = i >> 5, c = (i & 31) << 2;
            *(uint4*)&Ks[row * FQ_STRIDE + c] =
                *(const uint4*)&Kg[(size_t)(j * 64 + row) * D_ + c];
            *(uint4*)&Vs[row * FV_STRIDE + c] =
                *(const uint4*)&Vg[(size_t)(j * 64 + row) * D_ + c];
        }
        __syncthreads();

        // S = Q K^T : warp's 16 rows x 64 cols
        float S[8][4];
#pragma unroll
        for (int nt = 0; nt < 8; nt++)
#pragma unroll
            for (int q = 0; q < 4; q++) S[nt][q] = 0.f;

#pragma unroll
        for (int k8 = 0; k8 < 128; k8 += 8) {
            uint32_t a0 = Qs[(m0 + lr) * FQ_STRIDE + k8 + lc];
            uint32_t a1 = Qs[(m0 + 8 + lr) * FQ_STRIDE + k8 + lc];
            uint32_t a2 = Qs[(m0 + lr) * FQ_STRIDE + k8 + 4 + lc];
            uint32_t a3 = Qs[(m0 + 8 + lr) * FQ_STRIDE + k8 + 4 + lc];
#pragma unroll
            for (int nt = 0; nt < 8; nt++) {
                uint32_t b0 = Ks[(nt * 8 + lr) * FQ_STRIDE + k8 + lc];
                uint32_t b1 = Ks[(nt * 8 + lr) * FQ_STRIDE + k8 + 4 + lc];
                mma8(S[nt], a0, a1, a2, a3, b0, b1);
            }
        }

        // causal mask (only tiles that touch the diagonal)
        if (j >= 2 * ti) {
            const int row1 = ti * 128 + m0 + lr;
            const int row2 = row1 + 8;
#pragma unroll
            for (int nt = 0; nt < 8; nt++) {
                int c0 = j * 64 + nt * 8 + 2 * lc;
                if (c0     > row1) S[nt][0] = -3.0e38f;
                if (c0 + 1 > row1) S[nt][1] = -3.0e38f;
                if (c0     > row2) S[nt][2] = -3.0e38f;
                if (c0 + 1 > row2) S[nt][3] = -3.0e38f;
            }
        }

        // online softmax (rows r1 = m0+lr, r2 = r1+8); quad lanes share a row
        float mt1 = -3.0e38f, mt2 = -3.0e38f;
#pragma unroll
        for (int nt = 0; nt < 8; nt++) {
            mt1 = fmaxf(mt1, fmaxf(S[nt][0], S[nt][1]));
            mt2 = fmaxf(mt2, fmaxf(S[nt][2], S[nt][3]));
        }
        mt1 = fmaxf(mt1, __shfl_xor_sync(0xffffffffu, mt1, 1));
        mt1 = fmaxf(mt1, __shfl_xor_sync(0xffffffffu, mt1, 2));
        mt2 = fmaxf(mt2, __shfl_xor_sync(0xffffffffu, mt2, 1));
        mt2 = fmaxf(mt2, __shfl_xor_sync(0xffffffffu, mt2, 2));
        const float mn1 = fmaxf(m1, mt1);
        const float mn2 = fmaxf(m2, mt2);
        const float al1 = __expf(m1 - mn1);
        const float al2 = __expf(m2 - mn2);

        float lt1 = 0.f, lt2 = 0.f;
        uint32_t* prow1 = &Ps[(m0 + lr) * FP_STRIDE + 2 * lc];
        uint32_t* prow2 = &Ps[(m0 + 8 + lr) * FP_STRIDE + 2 * lc];
#pragma unroll
        for (int nt = 0; nt < 8; nt++) {
            float p0 = __expf(S[nt][0] - mn1);
            float p1 = __expf(S[nt][1] - mn1);
            float p2 = __expf(S[nt][2] - mn2);
            float p3 = __expf(S[nt][3] - mn2);
            lt1 += p0 + p1;
            lt2 += p2 + p3;
            *(uint2*)&prow1[nt * 8] = make_uint2(f2tf(p0), f2tf(p1));
            *(uint2*)&prow2[nt * 8] = make_uint2(f2tf(p2), f2tf(p3));
        }
        lt1 += __shfl_xor_sync(0xffffffffu, lt1, 1);
        lt1 += __shfl_xor_sync(0xffffffffu, lt1, 2);
        lt2 += __shfl_xor_sync(0xffffffffu, lt2, 1);
        lt2 += __shfl_xor_sync(0xffffffffu, lt2, 2);
        l1 = l1 * al1 + lt1;
        l2 = l2 * al2 + lt2;
        m1 = mn1; m2 = mn2;

#pragma unroll
        for (int nt = 0; nt < 16; nt++) {
            O[nt][0] *= al1; O[nt][1] *= al1;
            O[nt][2] *= al2; O[nt][3] *= al2;
        }
        __syncwarp();   // P rows for this warp's m-tile are produced by this warp only

        // O += P V : warp's 16 rows x 128 d, k = 64
#pragma unroll
        for (int k8 = 0; k8 < 64; k8 += 8) {
            uint32_t a0 = Ps[(m0 + lr) * FP_STRIDE + k8 + lc];
            uint32_t a1 = Ps[(m0 + 8 + lr) * FP_STRIDE + k8 + lc];
            uint32_t a2 = Ps[(m0 + lr) * FP_STRIDE + k8 + 4 + lc];
            uint32_t a3 = Ps[(m0 + 8 + lr) * FP_STRIDE + k8 + 4 + lc];
#pragma unroll
            for (int nt = 0; nt < 16; nt++) {
                uint32_t b0 = Vs[(k8 + lc) * FV_STRIDE + nt * 8 + lr];
                uint32_t b1 = Vs[(k8 + 4 + lc) * FV_STRIDE + nt * 8 + lr];
                mma8(O[nt], a0, a1, a2, a3, b0, b1);
            }
        }
    }

    // epilogue
    const float inv1 = 1.f / l1;
    const float inv2 = 1.f / l2;
    const int n1 = ti * 128 + m0 + lr;
    const int n2 = n1 + 8;
    float* out1 = &g_attn[((size_t)(b * N_ + n1)) * INNER + h * D_];
    float* out2 = &g_attn[((size_t)(b * N_ + n2)) * INNER + h * D_];
#pragma unroll
    for (int nt = 0; nt < 16; nt++) {
        int col = nt * 8 + 2 * lc;
        *(float2*)&out1[col] = make_float2(O[nt][0] * inv1, O[nt][1] * inv1);
        *(float2*)&out2[col] = make_float2(O[nt][2] * inv2, O[nt][3] * inv2);
    }
}

// ---------------- layernorm ----------------
__global__ __launch_bounds__(256) void ln_kernel(const float* __restrict__ in,
                                                 const float* __restrict__ g,
                                                 float* __restrict__ out)
{
    const int row = blockIdx.x;
    const int tid = threadIdx.x;
    const float* x = in + (size_t)row * DIM_;

    float v[8];
    float s = 0.f, ss = 0.f;
#pragma unroll
    for (int i = 0; i < 8; i++) {
        v[i] = x[tid + i * 256];
        s += v[i]; ss += v[i] * v[i];
    }
#pragma unroll
    for (int o = 16; o > 0; o >>= 1) {
        s  += __shfl_xor_sync(0xffffffffu, s,  o);
        ss += __shfl_xor_sync(0xffffffffu, ss, o);
    }
    __shared__ float sbuf[16];
    if ((tid & 31) == 0) { sbuf[tid >> 5] = s; sbuf[8 + (tid >> 5)] = ss; }
    __syncthreads();
    s = 0.f; ss = 0.f;
#pragma unroll
    for (int i = 0; i < 8; i++) { s += sbuf[i]; ss += sbuf[8 + i]; }

    const float mean = s * (1.f / DIM_);
    const float var  = ss * (1.f / DIM_) - mean * mean;
    const float inv  = rsqrtf(var + 1e-5f);
#pragma unroll
    for (int i = 0; i < 8; i++) {
        int c = tid + i * 256;
        out[(size_t)row * DIM_ + c] = (v[i] - mean) * inv * g[c];
    }
}

// ---------------- launch ----------------
extern "C" void kernel_launch(void* const* d_in, const int* in_sizes, int n_in,
                              void* d_out, int out_size)
{
    (void)in_sizes; (void)n_in; (void)out_size;
    const float* x     = (const float*)d_in[0];
    const float* rope  = (const float*)d_in[2];
    const float* w_qkv = (const float*)d_in[3];
    const float* w_out = (const float*)d_in[4];
    const float* g     = (const float*)d_in[5];
    float* out = (float*)d_out;

    float *qkv, *attn, *proj;
    cudaGetSymbolAddress((void**)&qkv,  g_qkv);
    cudaGetSymbolAddress((void**)&attn, g_attn);
    cudaGetSymbolAddress((void**)&proj, g_proj);

    cudaFuncSetAttribute(flash_tf32,
                         cudaFuncAttributeMaxDynamicSharedMemorySize, FSMEM);

    // 1) qkv = x @ w_qkv^T
    gemm_tf32<<<dim3(E3_ / 128, M_ / 128), 256>>>(x, w_qkv, qkv, M_, E3_, 2048);
    // 2) RoPE + scale + transpose (tf32 rounding)
    rotary_kernel<<<dim3(N_, B_ * H_), 128>>>(qkv, rope);
    // 3) causal flash attention (tf32 mma)
    flash_tf32<<<dim3(N_ / 128, B_ * H_), 256, FSMEM>>>();
    // 4) proj = attn @ w_out^T
    gemm_tf32<<<dim3(DIM_ / 128, M_ / 128), 256>>>(attn, w_out, proj, M_, DIM_, 2048);
    // 5) layernorm
    ln_kernel<<<M_, 256>>>(proj, g, out);
}